// round 2
// baseline (speedup 1.0000x reference)
#include <cuda_runtime.h>
#include <math.h>

#define C_DIM 320
#define B_DIM 8
#define T_TOP 2048
#define NDIV 11.0

#define POOL_FLOATS (B_DIM * C_DIM * 2047)
__device__ float g_z1p[POOL_FLOATS];
__device__ float g_z2p[POOL_FLOATS];
__device__ double g_acc[2];   // [0]=inst, [1]=temp

__device__ __forceinline__ void fma2(unsigned long long& d,
                                     unsigned long long a,
                                     unsigned long long b) {
    asm("fma.rn.f32x2 %0, %1, %2, %0;" : "+l"(d) : "l"(a), "l"(b));
}
__device__ __forceinline__ float2 upk(unsigned long long u) {
    float2 f;
    asm("mov.b64 {%0, %1}, %2;" : "=f"(f.x), "=f"(f.y) : "l"(u));
    return f;
}

__global__ void zero_kernel() { g_acc[0] = 0.0; g_acc[1] = 0.0; }

__global__ void pool_kernel(const float* __restrict__ s1, const float* __restrict__ s2,
                            float* __restrict__ d1, float* __restrict__ d2, int Tin) {
    int Tout = Tin >> 1;
    int n = B_DIM * C_DIM * Tout;
    for (int i = blockIdx.x * blockDim.x + threadIdx.x; i < n;
         i += gridDim.x * blockDim.x) {
        int bc = i / Tout;
        int t  = i - bc * Tout;
        int s  = bc * Tin + 2 * t;
        d1[i] = fmaxf(s1[s], s1[s + 1]);
        d2[i] = fmaxf(s2[s], s2[s + 1]);
    }
}

__global__ void fin_kernel(float* out) {
    double inst = g_acc[0] / NDIV;
    double temp = g_acc[1] / NDIV;
    out[0] = (float)(0.5 * inst + 0.5 * temp);
    out[1] = (float)inst;
    out[2] = (float)temp;
}

// -------- instance loss: per time t, 16 vectors (z1 b=0..7, z2 b=0..7), dim 320 --------
__global__ void inst_kernel(const float* __restrict__ z1, const float* __restrict__ z2,
                            int T, double scale) {
    __shared__ float sm[16][8][64];
    int tid  = threadIdx.x;
    int lane = tid & 31;
    int grp  = tid >> 5;
    int t0   = blockIdx.x * 64;
    int row0 = grp * 2, row1 = row0 + 1;

    unsigned long long a0[16], a1[16];
#pragma unroll
    for (int m = 0; m < 16; m++) { a0[m] = 0ull; a1[m] = 0ull; }

    for (int cc = 0; cc < C_DIM; cc += 8) {
        __syncthreads();
        for (int e = tid; e < 16 * 8 * 64; e += 256) {
            int t = e & 63, c = (e >> 6) & 7, v = e >> 9;
            int gt = t0 + t;
            float val = 0.f;
            if (gt < T) {
                int gc = cc + c;
                val = (v < 8) ? z1[(v * C_DIM + gc) * T + gt]
                              : z2[((v - 8) * C_DIM + gc) * T + gt];
            }
            sm[v][c][t] = val;
        }
        __syncthreads();
#pragma unroll
        for (int c = 0; c < 8; c++) {
            unsigned long long x0 =
                *reinterpret_cast<const unsigned long long*>(&sm[row0][c][2 * lane]);
            unsigned long long x1 =
                *reinterpret_cast<const unsigned long long*>(&sm[row1][c][2 * lane]);
#pragma unroll
            for (int m = 0; m < 16; m++) {
                unsigned long long y =
                    *reinterpret_cast<const unsigned long long*>(&sm[m][c][2 * lane]);
                fma2(a0[m], x0, y);
                fma2(a1[m], x1, y);
            }
        }
    }

    float contrib = 0.f;
    int ta = t0 + 2 * lane, tb = ta + 1;
#pragma unroll
    for (int rsel = 0; rsel < 2; rsel++) {
        unsigned long long* ar = rsel ? a1 : a0;
        int row = rsel ? row1 : row0;
        int pr = row ^ 8;
        float va[16], vb[16];
#pragma unroll
        for (int m = 0; m < 16; m++) { float2 f = upk(ar[m]); va[m] = f.x; vb[m] = f.y; }
        float mxa = -INFINITY, mxb = -INFINITY, pa = 0.f, pb = 0.f;
#pragma unroll
        for (int m = 0; m < 16; m++) {
            if (m == pr) { pa = va[m]; pb = vb[m]; }
            if (m != row) { mxa = fmaxf(mxa, va[m]); mxb = fmaxf(mxb, vb[m]); }
        }
        float sa = 0.f, sb = 0.f;
#pragma unroll
        for (int m = 0; m < 16; m++) {
            if (m != row) { sa += __expf(va[m] - mxa); sb += __expf(vb[m] - mxb); }
        }
        if (ta < T) contrib += mxa + logf(sa) - pa;
        if (tb < T) contrib += mxb + logf(sb) - pb;
    }
#pragma unroll
    for (int m = 16; m >= 1; m >>= 1)
        contrib += __shfl_xor_sync(0xffffffffu, contrib, m);
    if (lane == 0) atomicAdd(&g_acc[0], (double)contrib * scale);
}

// -------- temporal loss: per b, Gram of 2T x 320 with flash-lse --------
#define BM 128
#define BN 64
#define ASTR 324
#define BSTR 36
#define SMEM_BYTES ((BM * ASTR + BN * BSTR + BM) * 4)

__global__ void __launch_bounds__(256, 1)
temp_kernel(const float* __restrict__ z1, const float* __restrict__ z2,
            int T, double scale) {
    extern __shared__ float smem[];
    float* As   = smem;
    float* Bs   = smem + BM * ASTR;
    float* posv = Bs + BN * BSTR;

    int tid = threadIdx.x;
    int tx = tid & 15, ty = tid >> 4;
    int twoT = 2 * T;
    int r0 = blockIdx.x * BM;
    int b  = blockIdx.y;
    const float* zb1 = z1 + (long)b * C_DIM * T;
    const float* zb2 = z2 + (long)b * C_DIM * T;

    for (int e = tid; e < BM * C_DIM; e += 256) {
        int r = e & (BM - 1), k = e >> 7;
        int grow = r0 + r;
        float v = 0.f;
        if (grow < twoT)
            v = (grow < T) ? zb1[k * T + grow] : zb2[k * T + grow - T];
        As[r * ASTR + k] = v;
    }
    if (tid < BM) posv[tid] = 0.f;
    __syncthreads();

    float m_run[8], s_run[8];
#pragma unroll
    for (int i = 0; i < 8; i++) { m_run[i] = -INFINITY; s_run[i] = 0.f; }

    for (int c0 = 0; c0 < twoT; c0 += BN) {
        unsigned long long acc2[8][4];
#pragma unroll
        for (int i = 0; i < 8; i++)
#pragma unroll
            for (int c = 0; c < 4; c++) acc2[i][c] = 0ull;

        for (int kc = 0; kc < C_DIM; kc += 32) {
            __syncthreads();
            for (int e = tid; e < BN * 32; e += 256) {
                int r = e & 63, k = e >> 6;
                int gcol = c0 + r;
                float v = 0.f;
                if (gcol < twoT)
                    v = (gcol < T) ? zb1[(kc + k) * T + gcol]
                                   : zb2[(kc + k) * T + gcol - T];
                Bs[r * BSTR + k] = v;
            }
            __syncthreads();
#pragma unroll
            for (int k4 = 0; k4 < 32; k4 += 4) {
                ulonglong2 bq[4];
#pragma unroll
                for (int c = 0; c < 4; c++)
                    bq[c] = *reinterpret_cast<const ulonglong2*>(
                        Bs + (tx + 16 * c) * BSTR + k4);
#pragma unroll
                for (int i = 0; i < 8; i++) {
                    ulonglong2 aq = *reinterpret_cast<const ulonglong2*>(
                        As + (ty + 16 * i) * ASTR + kc + k4);
#pragma unroll
                    for (int c = 0; c < 4; c++) {
                        fma2(acc2[i][c], aq.x, bq[c].x);
                        fma2(acc2[i][c], aq.y, bq[c].y);
                    }
                }
            }
        }

#pragma unroll
        for (int i = 0; i < 8; i++) {
            int lr = ty + 16 * i;
            int grow = r0 + lr;
            int prow = (grow < T) ? grow + T : grow - T;
            float v[4];
            float mt = -INFINITY;
#pragma unroll
            for (int c = 0; c < 4; c++) {
                float2 f = upk(acc2[i][c]);
                float val = f.x + f.y;
                int gcol = c0 + tx + 16 * c;
                if (gcol >= twoT || gcol == grow) val = -INFINITY;
                else if (gcol == prow) posv[lr] = val;
                v[c] = val;
                mt = fmaxf(mt, val);
            }
#pragma unroll
            for (int m = 8; m >= 1; m >>= 1)
                mt = fmaxf(mt, __shfl_xor_sync(0xffffffffu, mt, m));
            float st = 0.f;
#pragma unroll
            for (int c = 0; c < 4; c++)
                st += (v[c] > -INFINITY) ? __expf(v[c] - mt) : 0.f;
#pragma unroll
            for (int m = 8; m >= 1; m >>= 1)
                st += __shfl_xor_sync(0xffffffffu, st, m);
            if (mt > -INFINITY) {
                float nm = fmaxf(m_run[i], mt);
                s_run[i] = s_run[i] * __expf(m_run[i] - nm) + st * __expf(mt - nm);
                m_run[i] = nm;
            }
        }
    }
    __syncthreads();

    float local = 0.f;
    if (tx == 0) {
#pragma unroll
        for (int i = 0; i < 8; i++) {
            int lr = ty + 16 * i;
            int grow = r0 + lr;
            if (grow < twoT)
                local += m_run[i] + logf(s_run[i]) - posv[lr];
        }
    }
#pragma unroll
    for (int m = 16; m >= 1; m >>= 1)
        local += __shfl_xor_sync(0xffffffffu, local, m);
    if ((tid & 31) == 0) atomicAdd(&g_acc[1], (double)local * scale);
}

extern "C" void kernel_launch(void* const* d_in, const int* in_sizes, int n_in,
                              void* d_out, int out_size) {
    (void)in_sizes; (void)n_in; (void)out_size;
    const float* z1 = (const float*)d_in[0];
    const float* z2 = (const float*)d_in[1];
    float* out = (float*)d_out;

    float *p1 = nullptr, *p2 = nullptr;
    cudaGetSymbolAddress((void**)&p1, g_z1p);
    cudaGetSymbolAddress((void**)&p2, g_z2p);
    cudaFuncSetAttribute(temp_kernel,
                         cudaFuncAttributeMaxDynamicSharedMemorySize, SMEM_BYTES);

    zero_kernel<<<1, 1>>>();

    const float *s1 = z1, *s2 = z2;
    long off = 0;
    for (int lvl = 0; lvl <= 11; lvl++) {
        int T = T_TOP >> lvl;
        if (lvl > 0) {
            int Tin = T << 1;
            float* d1 = p1 + off;
            float* d2p = p2 + off;
            int n = B_DIM * C_DIM * T;
            int blk = (n + 255) / 256;
            if (blk > 1184) blk = 1184;
            pool_kernel<<<blk, 256>>>(s1, s2, d1, d2p, Tin);
            s1 = d1; s2 = d2p;
            off += (long)B_DIM * C_DIM * T;
        }
        double scale = 1.0 / (16.0 * (double)T);
        inst_kernel<<<(T + 63) / 64, 256>>>(s1, s2, T, scale);
        dim3 g((2 * T + BM - 1) / BM, B_DIM);
        temp_kernel<<<g, 256, SMEM_BYTES>>>(s1, s2, T, scale);
    }
    fin_kernel<<<1, 1>>>(out);
}

// round 4
// speedup vs baseline: 5.4120x; 5.4120x over previous
#include <cuda_runtime.h>
#include <cuda_bf16.h>
#include <cstdint>
#include <math.h>

#define C_DIM 320
#define B_DIM 8
#define T_TOP 2048
#define NDIV 11.0

// ---------------- scratch ----------------
#define POOL_FLOATS (B_DIM * C_DIM * 2047)
#define X_ELEMS (B_DIM * C_DIM * 8190)
__device__ float g_z1p[POOL_FLOATS];
__device__ float g_z2p[POOL_FLOATS];
__device__ __align__(256) __nv_bfloat16 g_xhi[X_ELEMS];
__device__ __align__(256) __nv_bfloat16 g_xlo[X_ELEMS];
__device__ double g_acc[2];   // [0]=inst, [1]=temp

// ---------------- PTX helpers (sm_80-era only) ----------------
__device__ __forceinline__ uint32_t smem_u32(const void* p) {
    uint32_t a;
    asm("{ .reg .u64 t; cvta.to.shared.u64 t, %1; cvt.u32.u64 %0, t; }" : "=r"(a) : "l"(p));
    return a;
}
__device__ __forceinline__ void ldmx4(uint32_t* r, uint32_t addr) {
    asm volatile("ldmatrix.sync.aligned.m8n8.x4.shared.b16 {%0,%1,%2,%3}, [%4];"
                 : "=r"(r[0]), "=r"(r[1]), "=r"(r[2]), "=r"(r[3]) : "r"(addr));
}
__device__ __forceinline__ void mma_bf16(float* c, const uint32_t* a,
                                         uint32_t b0, uint32_t b1) {
    asm volatile("mma.sync.aligned.m16n8k16.row.col.f32.bf16.bf16.f32 "
                 "{%0,%1,%2,%3}, {%4,%5,%6,%7}, {%8,%9}, {%0,%1,%2,%3};"
                 : "+f"(c[0]), "+f"(c[1]), "+f"(c[2]), "+f"(c[3])
                 : "r"(a[0]), "r"(a[1]), "r"(a[2]), "r"(a[3]), "r"(b0), "r"(b1));
}
__device__ __forceinline__ void cpa16(uint32_t dst, const void* src, bool valid) {
    int sz = valid ? 16 : 0;
    asm volatile("cp.async.cg.shared.global [%0], [%1], 16, %2;"
                 :: "r"(dst), "l"(src), "r"(sz));
}
#define CP_COMMIT() asm volatile("cp.async.commit_group;" ::: "memory")
#define CP_WAIT1()  asm volatile("cp.async.wait_group 1;" ::: "memory")
#define CP_WAIT0()  asm volatile("cp.async.wait_group 0;" ::: "memory")

// ---------------- trivial kernels ----------------
__global__ void zero_kernel() { g_acc[0] = 0.0; g_acc[1] = 0.0; }

__global__ void fin_kernel(float* out) {
    double inst = g_acc[0] / NDIV;
    double temp = g_acc[1] / NDIV;
    out[0] = (float)(0.5 * inst + 0.5 * temp);
    out[1] = (float)inst;
    out[2] = (float)temp;
}

__global__ void pool_kernel(const float* __restrict__ s1, const float* __restrict__ s2,
                            float* __restrict__ d1, float* __restrict__ d2, int Tin) {
    int Tout = Tin >> 1;
    int n = B_DIM * C_DIM * Tout;
    for (int i = blockIdx.x * blockDim.x + threadIdx.x; i < n;
         i += gridDim.x * blockDim.x) {
        int bc = i / Tout;
        int t  = i - bc * Tout;
        int s  = bc * Tin + 2 * t;
        d1[i] = fmaxf(s1[s], s1[s + 1]);
        d2[i] = fmaxf(s2[s], s2[s + 1]);
    }
}

// convert level to bf16 hi/lo, layout [b][row(2T)][c]
__global__ void convert_kernel(const float* __restrict__ z1, const float* __restrict__ z2,
                               int T, long xoff) {
    __shared__ float tile[32][33];
    int zsel = blockIdx.z & 1;
    int b = blockIdx.z >> 1;
    const float* src = (zsel ? z2 : z1) + (long)b * C_DIM * T;
    int t0 = blockIdx.x * 32, c0 = blockIdx.y * 32;
    int tx = threadIdx.x, ty = threadIdx.y;   // 32 x 8
#pragma unroll
    for (int j = 0; j < 4; j++) {
        int c = c0 + ty + 8 * j;
        int t = t0 + tx;
        tile[ty + 8 * j][tx] = (t < T) ? src[(long)c * T + t] : 0.f;
    }
    __syncthreads();
    long R = 2L * T;
#pragma unroll
    for (int j = 0; j < 4; j++) {
        int row = t0 + ty + 8 * j;
        int c = c0 + tx;
        if (row < T) {
            float x = tile[tx][ty + 8 * j];
            __nv_bfloat16 hi = __float2bfloat16(x);
            __nv_bfloat16 lo = __float2bfloat16(x - __bfloat162float(hi));
            long grow = zsel ? (T + row) : row;
            long idx = xoff + ((long)b * R + grow) * C_DIM + c;
            g_xhi[idx] = hi;
            g_xlo[idx] = lo;
        }
    }
}

// ---------------- instance loss, all levels in one launch ----------------
__global__ void inst_all_kernel(const float* __restrict__ z1, const float* __restrict__ z2) {
    __shared__ float sm[16][8][64];
    int rem = blockIdx.x;
    int T = T_TOP;
    int lvl = 0;
    while (true) {
        int nb = (T + 63) >> 6;
        if (rem < nb) break;
        rem -= nb;
        T >>= 1;
        lvl++;
    }
    const float *s1, *s2;
    if (lvl == 0) { s1 = z1; s2 = z2; }
    else {
        long off = (long)B_DIM * C_DIM * (T_TOP - 2 * T);
        s1 = g_z1p + off; s2 = g_z2p + off;
    }
    double scale = 1.0 / (16.0 * (double)T);

    int tid  = threadIdx.x;
    int lane = tid & 31;
    int grp  = tid >> 5;
    int t0   = rem * 64;
    int row0 = grp * 2, row1 = row0 + 1;

    float a0x[16], a0y[16], a1x[16], a1y[16];
#pragma unroll
    for (int m = 0; m < 16; m++) { a0x[m] = a0y[m] = a1x[m] = a1y[m] = 0.f; }

    for (int cc = 0; cc < C_DIM; cc += 8) {
        __syncthreads();
        for (int e = tid; e < 16 * 8 * 64; e += 256) {
            int t = e & 63, c = (e >> 6) & 7, v = e >> 9;
            int gt = t0 + t;
            float val = 0.f;
            if (gt < T) {
                int gc = cc + c;
                val = (v < 8) ? s1[((long)v * C_DIM + gc) * T + gt]
                              : s2[((long)(v - 8) * C_DIM + gc) * T + gt];
            }
            sm[v][c][t] = val;
        }
        __syncthreads();
#pragma unroll
        for (int c = 0; c < 8; c++) {
            float2 x0 = *reinterpret_cast<const float2*>(&sm[row0][c][2 * lane]);
            float2 x1 = *reinterpret_cast<const float2*>(&sm[row1][c][2 * lane]);
#pragma unroll
            for (int m = 0; m < 16; m++) {
                float2 y = *reinterpret_cast<const float2*>(&sm[m][c][2 * lane]);
                a0x[m] += x0.x * y.x; a0y[m] += x0.y * y.y;
                a1x[m] += x1.x * y.x; a1y[m] += x1.y * y.y;
            }
        }
    }

    float contrib = 0.f;
    int ta = t0 + 2 * lane, tb = ta + 1;
#pragma unroll
    for (int rsel = 0; rsel < 2; rsel++) {
        float* vx = rsel ? a1x : a0x;
        float* vy = rsel ? a1y : a0y;
        int row = rsel ? row1 : row0;
        int pr = row ^ 8;
        float mxa = -INFINITY, mxb = -INFINITY, pa = 0.f, pb = 0.f;
#pragma unroll
        for (int m = 0; m < 16; m++) {
            if (m == pr) { pa = vx[m]; pb = vy[m]; }
            if (m != row) { mxa = fmaxf(mxa, vx[m]); mxb = fmaxf(mxb, vy[m]); }
        }
        float sa = 0.f, sb = 0.f;
#pragma unroll
        for (int m = 0; m < 16; m++) {
            if (m != row) { sa += __expf(vx[m] - mxa); sb += __expf(vy[m] - mxb); }
        }
        if (ta < T) contrib += mxa + logf(sa) - pa;
        if (tb < T) contrib += mxb + logf(sb) - pb;
    }
#pragma unroll
    for (int m = 16; m >= 1; m >>= 1)
        contrib += __shfl_xor_sync(0xffffffffu, contrib, m);
    if (lane == 0) atomicAdd(&g_acc[0], (double)contrib * scale);
}

// ---------------- temporal loss: HMMA flash-Gram, all levels fused ----------------
// smem (bytes):
//  A_hi @0        : 128 x 328(pad) bf16 = 83968
//  A_lo @83968    : 83968
//  B bufs @167936 : 2 stages x (hi 10240 + lo 10240) = 40960   [128 x 40(pad) bf16]
//  partial @208896: float2[128][4] = 4096
//  pos @212992    : float[128] = 512
#define A_LO_REL 83968
#define B_BASE   167936
#define PART_OFF 208896
#define POS_OFF  212992
#define TEMP_SMEM 213504
#define NSTAGE 10   // K=320 in chunks of 32

__global__ void __launch_bounds__(256, 1)
temp_all_kernel() {
    extern __shared__ char smem[];
    uint32_t sb = smem_u32(smem);
    int tid = threadIdx.x;
    int wid = tid >> 5;
    int lane = tid & 31;

    // ---- resolve (lvl, tile, b) ----
    int rem = blockIdx.x;
    int T = T_TOP;
    int nb;
    while (true) {
        nb = (2 * T + 127) >> 7;
        if (rem < nb * 8) break;
        rem -= nb * 8;
        T >>= 1;
    }
    int b    = rem / nb;        // b slow: first nb CTAs share b=0's data
    int tile = rem % nb;
    int R = 2 * T;
    int r0 = tile * 128;
    long xoff = 5120L * (2L * T_TOP - 2L * T);
    double scale = 1.0 / (16.0 * (double)T);
    const __nv_bfloat16* Xh = g_xhi + xoff + (long)b * R * C_DIM;
    const __nv_bfloat16* Xl = g_xlo + xoff + (long)b * R * C_DIM;

    int warp_m = (wid >> 2) * 64;
    int warp_n = (wid & 3) * 32;
    int warp_cn = wid & 3;

    // ---- load A tile (once) ----
    for (int e = tid; e < 128 * 40; e += 256) {
        int row = e / 40;
        int ch  = e - row * 40;
        int grow = r0 + row;
        uint4 vh = make_uint4(0, 0, 0, 0), vl = make_uint4(0, 0, 0, 0);
        if (grow < R) {
            vh = *reinterpret_cast<const uint4*>(Xh + (long)grow * C_DIM + ch * 8);
            vl = *reinterpret_cast<const uint4*>(Xl + (long)grow * C_DIM + ch * 8);
        }
        *reinterpret_cast<uint4*>(smem + row * 656 + ch * 16) = vh;
        *reinterpret_cast<uint4*>(smem + A_LO_REL + row * 656 + ch * 16) = vl;
    }
    float* poss = reinterpret_cast<float*>(smem + POS_OFF);
    if (tid < 128) poss[tid] = 0.f;

    float m_run = -INFINITY, s_run = 0.f;   // valid in threads 0..127

    int ntiles = (R + 127) >> 7;
    for (int ct = 0; ct < ntiles; ct++) {
        int c0 = ct * 128;
        float acc[4][4][4];
#pragma unroll
        for (int mt = 0; mt < 4; mt++)
#pragma unroll
            for (int nt = 0; nt < 4; nt++)
#pragma unroll
                for (int q = 0; q < 4; q++) acc[mt][nt][q] = 0.f;

        // prefetch stage 0
        {
            uint32_t bb = sb + B_BASE;
            for (int e = tid; e < 1024; e += 256) {
                int hl = e >> 9, r2 = e & 511;
                int col = r2 >> 2, ch = r2 & 3;
                int gcol = c0 + col;
                bool v = gcol < R;
                const __nv_bfloat16* src =
                    (hl ? Xl : Xh) + (long)(v ? gcol : 0) * C_DIM + ch * 8;
                cpa16(bb + hl * 10240 + col * 80 + ch * 16, src, v);
            }
            CP_COMMIT();
        }

        for (int ks = 0; ks < NSTAGE; ks++) {
            if (ks + 1 < NSTAGE) {
                uint32_t bb = sb + B_BASE + ((ks + 1) & 1) * 20480;
                int kbase = (ks + 1) * 32;
                for (int e = tid; e < 1024; e += 256) {
                    int hl = e >> 9, r2 = e & 511;
                    int col = r2 >> 2, ch = r2 & 3;
                    int gcol = c0 + col;
                    bool v = gcol < R;
                    const __nv_bfloat16* src =
                        (hl ? Xl : Xh) + (long)(v ? gcol : 0) * C_DIM + kbase + ch * 8;
                    cpa16(bb + hl * 10240 + col * 80 + ch * 16, src, v);
                }
                CP_COMMIT();
                CP_WAIT1();
            } else {
                CP_WAIT0();
            }
            __syncthreads();

            uint32_t bbuf = sb + B_BASE + (ks & 1) * 20480;
            int kbase = ks * 32;
#pragma unroll
            for (int kk = 0; kk < 2; kk++) {
                int kg2 = kk * 16;
                uint32_t ah[4][4], al[4][4];
#pragma unroll
                for (int mt = 0; mt < 4; mt++) {
                    uint32_t addr = sb + (warp_m + mt * 16 + (lane & 15)) * 656 +
                                    (kbase + kg2) * 2 + ((lane >> 4) << 4);
                    ldmx4(ah[mt], addr);
                    ldmx4(al[mt], addr + A_LO_REL);
                }
                uint32_t bh[2][4], bl[2][4];
#pragma unroll
                for (int g = 0; g < 2; g++) {
                    uint32_t addr = bbuf + (warp_n + g * 16 + (lane & 15)) * 80 +
                                    kg2 * 2 + ((lane >> 4) << 4);
                    ldmx4(bh[g], addr);
                    ldmx4(bl[g], addr + 10240);
                }
#pragma unroll
                for (int mt = 0; mt < 4; mt++)
#pragma unroll
                    for (int nt = 0; nt < 4; nt++) {
                        int g = nt >> 1, s = nt & 1;
                        mma_bf16(acc[mt][nt], ah[mt], bh[g][s], bh[g][s + 2]);
                        mma_bf16(acc[mt][nt], ah[mt], bl[g][s], bl[g][s + 2]);
                        mma_bf16(acc[mt][nt], al[mt], bh[g][s], bh[g][s + 2]);
                    }
            }
            __syncthreads();
        }

        // ---- epilogue for this 128-col tile ----
        float2* part = reinterpret_cast<float2*>(smem + PART_OFF);
#pragma unroll
        for (int mt = 0; mt < 4; mt++)
#pragma unroll
            for (int h = 0; h < 2; h++) {
                int row_local = warp_m + mt * 16 + (lane >> 2) + 8 * h;
                int grow = r0 + row_local;
                int prow = (grow < T) ? grow + T : grow - T;
                float vals[8];
                float mloc = -INFINITY;
#pragma unroll
                for (int nt = 0; nt < 4; nt++)
#pragma unroll
                    for (int e2 = 0; e2 < 2; e2++) {
                        float v = acc[mt][nt][h * 2 + e2];
                        int gcol = c0 + warp_n + nt * 8 + (lane & 3) * 2 + e2;
                        bool bad = (gcol >= R) || (gcol == grow);
                        if (!bad && gcol == prow && grow < R) poss[row_local] = v;
                        v = bad ? -INFINITY : v;
                        vals[nt * 2 + e2] = v;
                        mloc = fmaxf(mloc, v);
                    }
                float sl = 0.f;
#pragma unroll
                for (int q = 0; q < 8; q++)
                    sl += (vals[q] > -INFINITY) ? __expf(vals[q] - mloc) : 0.f;
#pragma unroll
                for (int d = 1; d < 4; d <<= 1) {
                    float mo = __shfl_xor_sync(0xffffffffu, mloc, d);
                    float so = __shfl_xor_sync(0xffffffffu, sl, d);
                    float nm = fmaxf(mloc, mo);
                    float s1v = (mloc > -INFINITY) ? sl * __expf(mloc - nm) : 0.f;
                    float s2v = (mo > -INFINITY) ? so * __expf(mo - nm) : 0.f;
                    sl = s1v + s2v;
                    mloc = nm;
                }
                if ((lane & 3) == 0)
                    part[row_local * 4 + warp_cn] = make_float2(mloc, sl);
            }
        __syncthreads();
        if (tid < 128) {
#pragma unroll
            for (int w = 0; w < 4; w++) {
                float2 p = part[tid * 4 + w];
                if (p.y > 0.f) {
                    float nm = fmaxf(m_run, p.x);
                    float s0 = (s_run > 0.f) ? s_run * __expf(m_run - nm) : 0.f;
                    s_run = s0 + p.y * __expf(p.x - nm);
                    m_run = nm;
                }
            }
        }
        __syncthreads();
    }

    float contrib = 0.f;
    if (tid < 128) {
        int grow = r0 + tid;
        if (grow < R) contrib = m_run + logf(s_run) - poss[tid];
    }
#pragma unroll
    for (int m = 16; m >= 1; m >>= 1)
        contrib += __shfl_xor_sync(0xffffffffu, contrib, m);
    if (lane == 0 && wid < 4)
        atomicAdd(&g_acc[1], (double)contrib * scale);
}

// ---------------- host ----------------
extern "C" void kernel_launch(void* const* d_in, const int* in_sizes, int n_in,
                              void* d_out, int out_size) {
    (void)in_sizes; (void)n_in; (void)out_size;
    const float* z1 = (const float*)d_in[0];
    const float* z2 = (const float*)d_in[1];
    float* out = (float*)d_out;

    float *p1 = nullptr, *p2 = nullptr;
    cudaGetSymbolAddress((void**)&p1, g_z1p);
    cudaGetSymbolAddress((void**)&p2, g_z2p);
    cudaFuncSetAttribute(temp_all_kernel,
                         cudaFuncAttributeMaxDynamicSharedMemorySize, TEMP_SMEM);

    zero_kernel<<<1, 1>>>();

    // pools + converts
    {
        dim3 cb(32, 8);
        dim3 cg((T_TOP + 31) / 32, 10, 16);
        convert_kernel<<<cg, cb>>>(z1, z2, T_TOP, 0L);
    }
    const float *s1 = z1, *s2 = z2;
    for (int lvl = 1; lvl <= 11; lvl++) {
        int T = T_TOP >> lvl;
        long off = (long)B_DIM * C_DIM * (T_TOP - 2 * T);
        float* d1 = p1 + off;
        float* d2p = p2 + off;
        int n = B_DIM * C_DIM * T;
        int blk = (n + 255) / 256;
        if (blk > 1184) blk = 1184;
        pool_kernel<<<blk, 256>>>(s1, s2, d1, d2p, 2 * T);
        s1 = d1; s2 = d2p;
        long xoff = 5120L * (2L * T_TOP - 2L * T);
        dim3 cb(32, 8);
        dim3 cg((T + 31) / 32, 10, 16);
        convert_kernel<<<cg, cb>>>(s1, s2, T, xoff);
    }

    // instance loss: one launch
    {
        int nblk = 0;
        for (int lvl = 0; lvl <= 11; lvl++) nblk += ((T_TOP >> lvl) + 63) / 64;
        inst_all_kernel<<<nblk, 256>>>(z1, z2);
    }

    // temporal loss: one fused launch over all levels
    {
        int nblk = 0;
        for (int lvl = 0; lvl <= 11; lvl++) {
            int T = T_TOP >> lvl;
            nblk += ((2 * T + 127) >> 7) * 8;
        }
        temp_all_kernel<<<nblk, 256, TEMP_SMEM>>>();
    }

    fin_kernel<<<1, 1>>>(out);
}